// round 15
// baseline (speedup 1.0000x reference)
#include <cuda_runtime.h>
#include <cuda_fp16.h>
#include <math.h>
#include <stdint.h>

// Problem constants (fixed by the reference)
#define NN 50000
#define EE 200000
#define DD 384
#define HH 2
#define DHH 192

#define SCAN_BLK 1024
#define NSCAN ((NN + SCAN_BLK - 1) / SCAN_BLK)   // 49

// ---------------- device scratch (allocation-free requirement) ----------------
__device__ __half g_q[(size_t)NN * DD];          // fp16 q/k/v
__device__ __half g_k[(size_t)NN * DD];
__device__ __half g_v[(size_t)NN * DD];
__device__ float  g_tmp[(size_t)NN * DD];

__device__ int   g_deg[NN];
__device__ int   g_rowptr[NN + 1];
__device__ int   g_cursor[NN];
__device__ int   g_blocksum[NSCAN];
__device__ int   g_esrc[EE];
__device__ float g_eea[EE];

__device__ __half g_emb[(size_t)NN * DD];        // fp16(A)
__device__ __half g_agg[(size_t)NN * DD];        // fp16(agg)
__device__ __half g_wt[(size_t)3 * DD * DD];     // [WQ|WK|WV]^T  [1152(N), 384(K)]
__device__ __half g_wo[(size_t)DD * DD];         // WO^T [384, 384]

// ---------------- PTX helpers (baseline features only; PTX target is compute_103) ----------------
__device__ __forceinline__ uint32_t smem_to_u32(const void* p) {
    uint32_t a;
    asm("{ .reg .u64 t; cvta.to.shared.u64 t, %1; cvt.u32.u64 %0, t; }" : "=r"(a) : "l"(p));
    return a;
}
__device__ __forceinline__ void ldsm_x4(uint32_t* r, uint32_t addr) {
    asm volatile("ldmatrix.sync.aligned.m8n8.x4.shared.b16 {%0,%1,%2,%3}, [%4];"
        : "=r"(r[0]), "=r"(r[1]), "=r"(r[2]), "=r"(r[3]) : "r"(addr));
}
__device__ __forceinline__ void mma_f16(float* c, const uint32_t* a, const uint32_t* b) {
    asm volatile(
        "mma.sync.aligned.m16n8k16.row.col.f32.f16.f16.f32 "
        "{%0,%1,%2,%3}, {%4,%5,%6,%7}, {%8,%9}, {%0,%1,%2,%3};"
        : "+f"(c[0]), "+f"(c[1]), "+f"(c[2]), "+f"(c[3])
        : "r"(a[0]), "r"(a[1]), "r"(a[2]), "r"(a[3]), "r"(b[0]), "r"(b[1]));
}
__device__ __forceinline__ void cp16(uint32_t dst, const void* src, bool valid) {
    int sz = valid ? 16 : 0;
    asm volatile("cp.async.cg.shared.global [%0], [%1], 16, %2;"
        :: "r"(dst), "l"(src), "r"(sz) : "memory");
}

// smem geometry: 2 operand arrays (A, B), 128 rows x 80B pitch, double-buffered
#define PITCH 80
#define ARR   10240          // 128 * 80
#define STG   20480          // 2 * ARR
#define SM_TOTAL (2 * STG)   // 40960

// ---------------- fp16 HMMA GEMM, dual epilogue ----------------
// If H0 != nullptr: C stored as fp16 into H0/H1/H2 (QKV path, no resid).
// Else: C stored as fp32 into Cf (+resid)   (O-GEMM path).
__global__ __launch_bounds__(256)
void gemm_tc(const __half* __restrict__ A, const __half* __restrict__ Bt,
             __half* __restrict__ H0, __half* __restrict__ H1, __half* __restrict__ H2,
             float* __restrict__ Cf, int M, const float* __restrict__ resid)
{
    extern __shared__ char smem[];
    const uint32_t sb = smem_to_u32(smem);
    const int tid = threadIdx.x;
    const int wid = tid >> 5;
    const int lane = tid & 31;
    const int warp_m = wid & 1;
    const int warp_n = wid >> 1;
    const int rowBase = blockIdx.y * 128;
    const int mat = blockIdx.x / 3;
    const int colBase = (blockIdx.x % 3) * 128;
    const int btRowBase = blockIdx.x * 128;

    float acc[4][4][4];
#pragma unroll
    for (int i = 0; i < 4; i++)
#pragma unroll
        for (int j = 0; j < 4; j++)
#pragma unroll
            for (int l = 0; l < 4; l++) acc[i][j][l] = 0.0f;

    auto load_stage = [&](int buf, int s) {
        const int k0 = s * 32;
#pragma unroll
        for (int i = 0; i < 4; i++) {
            int id = i * 256 + tid;          // 0..1023
            int arr = id >> 9;               // 0..1
            int cid = id & 511;
            int row = cid >> 2;              // 0..127
            int c = cid & 3;                 // 16B chunk
            uint32_t dst = sb + buf * STG + arr * ARR + row * PITCH + c * 16;
            const __half* src;
            bool valid = true;
            if (arr == 0) {
                int gRow = rowBase + row;
                valid = (gRow < M);
                int gr = valid ? gRow : 0;
                src = A + (size_t)gr * DD + k0 + c * 8;
            } else {
                src = Bt + (size_t)(btRowBase + row) * DD + k0 + c * 8;
            }
            cp16(dst, src, valid);
        }
        asm volatile("cp.async.commit_group;" ::: "memory");
    };

    load_stage(0, 0);

    for (int s = 0; s < 12; s++) {
        asm volatile("cp.async.wait_group 0;" ::: "memory");
        __syncthreads();
        if (s + 1 < 12) load_stage((s + 1) & 1, s + 1);

        const uint32_t st = sb + (s & 1) * STG;
#pragma unroll
        for (int kk = 0; kk < 2; kk++) {
            uint32_t ah[4][4], bh[2][4];
            const int arow = warp_m * 64;
#pragma unroll
            for (int mt = 0; mt < 4; mt++) {
                uint32_t addr = st + (uint32_t)((arow + mt * 16 + (lane & 15)) * PITCH
                              + kk * 32 + ((lane >> 4) & 1) * 16);
                ldsm_x4(ah[mt], addr);
            }
#pragma unroll
            for (int p = 0; p < 2; p++) {
                int grp = lane >> 3;
                int row = warp_n * 32 + (p * 2 + (grp >> 1)) * 8 + (lane & 7);
                uint32_t addr = st + ARR + (uint32_t)(row * PITCH
                              + kk * 32 + (grp & 1) * 16);
                ldsm_x4(bh[p], addr);
            }
#pragma unroll
            for (int mt = 0; mt < 4; mt++) {
#pragma unroll
                for (int nt = 0; nt < 4; nt++) {
                    const uint32_t* B2 = &bh[nt >> 1][(nt & 1) * 2];
                    mma_f16(acc[mt][nt], ah[mt], B2);
                }
            }
        }
    }

    if (H0) {
        __half* H = (mat == 0) ? H0 : (mat == 1 ? H1 : H2);
#pragma unroll
        for (int mt = 0; mt < 4; mt++) {
            int r0 = rowBase + warp_m * 64 + mt * 16 + (lane >> 2);
#pragma unroll
            for (int nt = 0; nt < 4; nt++) {
                int col = colBase + warp_n * 32 + nt * 8 + (lane & 3) * 2;
#pragma unroll
                for (int half = 0; half < 2; half++) {
                    int r = r0 + half * 8;
                    if (r >= M) continue;
                    size_t off = (size_t)r * DD + col;
                    __half2 hv = __floats2half2_rn(acc[mt][nt][half * 2],
                                                   acc[mt][nt][half * 2 + 1]);
                    *reinterpret_cast<__half2*>(H + off) = hv;
                }
            }
        }
    } else {
#pragma unroll
        for (int mt = 0; mt < 4; mt++) {
            int r0 = rowBase + warp_m * 64 + mt * 16 + (lane >> 2);
#pragma unroll
            for (int nt = 0; nt < 4; nt++) {
                int col = colBase + warp_n * 32 + nt * 8 + (lane & 3) * 2;
#pragma unroll
                for (int half = 0; half < 2; half++) {
                    int r = r0 + half * 8;
                    if (r >= M) continue;
                    size_t off = (size_t)r * DD + col;
                    float2 v = make_float2(acc[mt][nt][half * 2], acc[mt][nt][half * 2 + 1]);
                    float2 rv = *reinterpret_cast<const float2*>(resid + off);
                    v.x += rv.x; v.y += rv.y;
                    *reinterpret_cast<float2*>(Cf + off) = v;
                }
            }
        }
    }
}

// ---------------- conversions ----------------
__global__ __launch_bounds__(256) void conv_emb(const float* __restrict__ emb) {
    int idx = blockIdx.x * 256 + threadIdx.x;
    if (idx >= NN * DD / 4) return;
    float4 x = reinterpret_cast<const float4*>(emb)[idx];
    __half2 a, b;
    a.x = __float2half_rn(x.x); a.y = __float2half_rn(x.y);
    b.x = __float2half_rn(x.z); b.y = __float2half_rn(x.w);
    uint2 v = make_uint2(*reinterpret_cast<uint32_t*>(&a), *reinterpret_cast<uint32_t*>(&b));
    reinterpret_cast<uint2*>(g_emb)[idx] = v;
}

__global__ __launch_bounds__(256) void conv_weights(
    const float* __restrict__ WQ, const float* __restrict__ WK,
    const float* __restrict__ WV, const float* __restrict__ WO)
{
    int idx = blockIdx.x * 256 + threadIdx.x;
    if (idx >= 4 * DD * DD) return;
    int mat = idx / (DD * DD);
    int rem = idx - mat * (DD * DD);
    int n = rem / DD;
    int k = rem - n * DD;
    const float* W = (mat == 0) ? WQ : (mat == 1 ? WK : (mat == 2 ? WV : WO));
    __half h = __float2half_rn(W[(size_t)k * DD + n]);
    if (mat < 3) g_wt[(size_t)mat * DD * DD + (size_t)n * DD + k] = h;
    else         g_wo[(size_t)n * DD + k] = h;
}

// ---------------- CSR build (side stream) ----------------
__global__ __launch_bounds__(256) void zero_deg() {
    int i = blockIdx.x * 256 + threadIdx.x;
    if (i < NN) g_deg[i] = 0;
}

__global__ __launch_bounds__(256) void hist_kernel(const int* __restrict__ dst) {
    int e = blockIdx.x * 256 + threadIdx.x;
    if (e < EE) atomicAdd(&g_deg[dst[e]], 1);
}

__device__ __forceinline__ int warp_incl_scan(int x, int lane) {
#pragma unroll
    for (int off = 1; off < 32; off <<= 1) {
        int v = __shfl_up_sync(0xffffffffu, x, off);
        if (lane >= off) x += v;
    }
    return x;
}

__global__ __launch_bounds__(1024) void scanA() {
    __shared__ int swarp[32];
    const int tid = threadIdx.x;
    const int w = tid >> 5, lane = tid & 31;
    int idx = blockIdx.x * 1024 + tid;
    int x = (idx < NN) ? g_deg[idx] : 0;
    int incl = warp_incl_scan(x, lane);
    if (lane == 31) swarp[w] = incl;
    __syncthreads();
    if (w == 0) {
        int t = swarp[lane];
        t = warp_incl_scan(t, lane);
        swarp[lane] = t;
    }
    __syncthreads();
    int woff = (w > 0) ? swarp[w - 1] : 0;
    incl += woff;
    if (idx < NN) g_rowptr[idx] = incl;
    if (tid == 1023) g_blocksum[blockIdx.x] = incl;
}

__global__ __launch_bounds__(64) void scanB() {
    __shared__ int sh[64];
    const int tid = threadIdx.x;
    int v = (tid < NSCAN) ? g_blocksum[tid] : 0;
    sh[tid] = v;
    for (int off = 1; off < 64; off <<= 1) {
        __syncthreads();
        int t = (tid >= off) ? sh[tid - off] : 0;
        __syncthreads();
        sh[tid] += t;
    }
    __syncthreads();
    if (tid < NSCAN) g_blocksum[tid] = sh[tid] - v;  // exclusive
    if (tid == 63) g_rowptr[NN] = sh[63];
}

__global__ __launch_bounds__(1024) void scanC() {
    int idx = blockIdx.x * 1024 + threadIdx.x;
    if (idx >= NN) return;
    int ex = g_blocksum[blockIdx.x] + g_rowptr[idx] - g_deg[idx];
    g_rowptr[idx] = ex;
    g_cursor[idx] = ex;
}

__global__ __launch_bounds__(256) void scatter_kernel(
    const int* __restrict__ src, const int* __restrict__ dst,
    const float* __restrict__ eattr)
{
    int e = blockIdx.x * 256 + threadIdx.x;
    if (e >= EE) return;
    int t = dst[e];
    int pos = atomicAdd(&g_cursor[t], 1);
    g_esrc[pos] = src[e];
    g_eea[pos] = eattr[e];
}

// ---------------- fused attention aggregate: warp per (node, head), half2 ----------------
__global__ __launch_bounds__(256) void node_fused(const float* __restrict__ WE) {
    const int gw = blockIdx.x * 8 + (threadIdx.x >> 5);
    const int n = gw >> 1;
    if (n >= NN) return;
    const int h = gw & 1;
    const int lane = threadIdx.x & 31;
    const int hb2 = h * (DHH / 2);                 // head offset in half2 units
    const size_t rowH2 = (size_t)n * (DD / 2) + hb2;

    float2 qv[3], we2[3];
    const __half2* qrow = reinterpret_cast<const __half2*>(g_q) + rowH2;
    const float* weh = WE + h * DHH;
#pragma unroll
    for (int j = 0; j < 3; j++) {
        int f = lane + 32 * j;
        qv[j] = __half22float2(qrow[f]);
        we2[j] = *reinterpret_cast<const float2*>(weh + 2 * f);
    }

    // qe = q_h . WE_h
    float qe = 0.f;
#pragma unroll
    for (int j = 0; j < 3; j++) qe += qv[j].x * we2[j].x + qv[j].y * we2[j].y;
#pragma unroll
    for (int o = 16; o > 0; o >>= 1) qe += __shfl_xor_sync(0xffffffffu, qe, o);

    const int beg = g_rowptr[n];
    const int end = g_rowptr[n + 1];

    float m0 = -3.0e38f, den = 0.f, sexa = 0.f;
    float2 acc[3];
#pragma unroll
    for (int j = 0; j < 3; j++) acc[j] = make_float2(0.f, 0.f);

    const float SCL = 0.07216878364870323f;  // 1/sqrt(192)

    for (int i = beg; i < end; i++) {
        const int s = g_esrc[i];
        const float ea = g_eea[i];
        const __half2* krow = reinterpret_cast<const __half2*>(g_k) + (size_t)s * (DD / 2) + hb2;
        const __half2* vrow = reinterpret_cast<const __half2*>(g_v) + (size_t)s * (DD / 2) + hb2;

        float2 kv[3], vv[3];
#pragma unroll
        for (int j = 0; j < 3; j++) {
            int f = lane + 32 * j;
            kv[j] = __half22float2(krow[f]);
            vv[j] = __half22float2(vrow[f]);
        }
        float ds = 0.f;
#pragma unroll
        for (int j = 0; j < 3; j++) ds += qv[j].x * kv[j].x + qv[j].y * kv[j].y;
#pragma unroll
        for (int o = 16; o > 0; o >>= 1) ds += __shfl_xor_sync(0xffffffffu, ds, o);
        float s0 = (ds + ea * qe) * SCL;

        float nm = fmaxf(m0, s0);
        float sc = __expf(m0 - nm);
        float ex = __expf(s0 - nm);
        den = den * sc + ex;
        sexa = sexa * sc + ex * ea;
#pragma unroll
        for (int j = 0; j < 3; j++) {
            acc[j].x = acc[j].x * sc + ex * vv[j].x;
            acc[j].y = acc[j].y * sc + ex * vv[j].y;
        }
        m0 = nm;
    }

    const float inv = 1.0f / (den + 1e-16f);
    __half2* aout = reinterpret_cast<__half2*>(g_agg) + rowH2;
#pragma unroll
    for (int j = 0; j < 3; j++) {
        int f = lane + 32 * j;
        float ox = (acc[j].x + sexa * we2[j].x) * inv;
        float oy = (acc[j].y + sexa * we2[j].y) * inv;
        aout[f] = __floats2half2_rn(ox, oy);
    }
}

// ---------------- layernorm: warp per row, float4 ----------------
__global__ __launch_bounds__(256) void ln_kernel(
    const float* __restrict__ gw, const float* __restrict__ bw,
    float* __restrict__ out)
{
    const int n = blockIdx.x * 8 + (threadIdx.x >> 5);
    if (n >= NN) return;
    const int lane = threadIdx.x & 31;
    const float4* x = reinterpret_cast<const float4*>(g_tmp + (size_t)n * DD);
    float4 v[3];
    float su = 0.f, sq = 0.f;
#pragma unroll
    for (int j = 0; j < 3; j++) {
        v[j] = x[lane + 32 * j];
        su += v[j].x + v[j].y + v[j].z + v[j].w;
        sq += v[j].x * v[j].x + v[j].y * v[j].y + v[j].z * v[j].z + v[j].w * v[j].w;
    }
#pragma unroll
    for (int o = 16; o > 0; o >>= 1) {
        su += __shfl_xor_sync(0xffffffffu, su, o);
        sq += __shfl_xor_sync(0xffffffffu, sq, o);
    }
    float mu = su * (1.0f / DD);
    float var = sq * (1.0f / DD) - mu * mu;
    float inv = rsqrtf(var + 1e-5f);
    const float4* g4 = reinterpret_cast<const float4*>(gw);
    const float4* b4 = reinterpret_cast<const float4*>(bw);
    float4* o4 = reinterpret_cast<float4*>(out + (size_t)n * DD);
#pragma unroll
    for (int j = 0; j < 3; j++) {
        float4 g = g4[lane + 32 * j];
        float4 b = b4[lane + 32 * j];
        float4 r;
        r.x = (v[j].x - mu) * inv * g.x + b.x;
        r.y = (v[j].y - mu) * inv * g.y + b.y;
        r.z = (v[j].z - mu) * inv * g.z + b.z;
        r.w = (v[j].w - mu) * inv * g.w + b.w;
        o4[lane + 32 * j] = r;
    }
}

// ---------------- launch ----------------
extern "C" void kernel_launch(void* const* d_in, const int* in_sizes, int n_in,
                              void* d_out, int out_size)
{
    const float* emb   = (const float*)d_in[0];
    const int*   eidx  = (const int*)  d_in[1];
    const float* eattr = (const float*)d_in[2];
    const float* WQ    = (const float*)d_in[3];
    const float* WK    = (const float*)d_in[4];
    const float* WV    = (const float*)d_in[5];
    const float* WE    = (const float*)d_in[6];
    const float* WO    = (const float*)d_in[7];
    const float* ln_g  = (const float*)d_in[8];
    const float* ln_b  = (const float*)d_in[9];
    float* out = (float*)d_out;

    const int* src = eidx;
    const int* dst = eidx + EE;

    static bool inited = false;
    static cudaStream_t s_side;
    static cudaEvent_t ev_fork, ev_join, ev_w;
    if (!inited) {
        cudaFuncSetAttribute(gemm_tc, cudaFuncAttributeMaxDynamicSharedMemorySize, SM_TOTAL);
        cudaStreamCreateWithFlags(&s_side, cudaStreamNonBlocking);
        cudaEventCreateWithFlags(&ev_fork, cudaEventDisableTiming);
        cudaEventCreateWithFlags(&ev_join, cudaEventDisableTiming);
        cudaEventCreateWithFlags(&ev_w, cudaEventDisableTiming);
        inited = true;
    }

    float *dtmp;
    __half *dq, *dk, *dv, *demb, *dagg, *dwt, *dwo;
    cudaGetSymbolAddress((void**)&dq,   g_q);
    cudaGetSymbolAddress((void**)&dk,   g_k);
    cudaGetSymbolAddress((void**)&dv,   g_v);
    cudaGetSymbolAddress((void**)&dtmp, g_tmp);
    cudaGetSymbolAddress((void**)&demb, g_emb);
    cudaGetSymbolAddress((void**)&dagg, g_agg);
    cudaGetSymbolAddress((void**)&dwt,  g_wt);
    cudaGetSymbolAddress((void**)&dwo,  g_wo);

    // ---- fork: weights conversion + CSR build on side stream ----
    cudaEventRecord(ev_fork, 0);
    cudaStreamWaitEvent(s_side, ev_fork, 0);
    conv_weights<<<(4 * DD * DD + 255) / 256, 256, 0, s_side>>>(WQ, WK, WV, WO);
    cudaEventRecord(ev_w, s_side);
    zero_deg<<<(NN + 255) / 256, 256, 0, s_side>>>();
    hist_kernel<<<(EE + 255) / 256, 256, 0, s_side>>>(dst);
    scanA<<<NSCAN, 1024, 0, s_side>>>();
    scanB<<<1, 64, 0, s_side>>>();
    scanC<<<NSCAN, 1024, 0, s_side>>>();
    scatter_kernel<<<(EE + 255) / 256, 256, 0, s_side>>>(src, dst, eattr);
    cudaEventRecord(ev_join, s_side);

    // ---- main stream: emb conversion + QKV projections (fp16 out) ----
    conv_emb<<<(NN * DD / 4 + 255) / 256, 256>>>(emb);
    cudaStreamWaitEvent(0, ev_w, 0);

    const int MT = (NN + 127) / 128;
    gemm_tc<<<dim3(9, MT), 256, SM_TOTAL>>>(demb, dwt,
                                            dq, dk, dv, nullptr, NN, nullptr);

    // ---- join, then fused attention ----
    cudaStreamWaitEvent(0, ev_join, 0);
    node_fused<<<(2 * NN + 7) / 8, 256>>>(WE);

    // output projection + residual (fp32 out)
    gemm_tc<<<dim3(3, MT), 256, SM_TOTAL>>>(dagg, dwo,
                                            nullptr, nullptr, nullptr, dtmp, NN, emb);

    // layernorm -> out
    ln_kernel<<<(NN + 7) / 8, 256>>>(ln_g, ln_b, out);
}

// round 16
// speedup vs baseline: 1.4831x; 1.4831x over previous
#include <cuda_runtime.h>
#include <cuda_fp16.h>
#include <math.h>
#include <stdint.h>

// Problem constants (fixed by the reference)
#define NN 50000
#define EE 200000
#define DD 384
#define HH 2
#define DHH 192

#define SCAN_BLK 1024
#define NSCAN ((NN + SCAN_BLK - 1) / SCAN_BLK)   // 49

// ---------------- device scratch (allocation-free requirement) ----------------
__device__ __half g_q[(size_t)NN * DD];          // fp16 q/k/v
__device__ __half g_k[(size_t)NN * DD];
__device__ __half g_v[(size_t)NN * DD];
__device__ float  g_tmp[(size_t)NN * DD];

__device__ int   g_deg[NN];
__device__ int   g_rowptr[NN + 1];
__device__ int   g_cursor[NN];
__device__ int   g_blocksum[NSCAN];
__device__ int   g_esrc[EE];
__device__ float g_eea[EE];

__device__ __half g_emb[(size_t)NN * DD];        // fp16(A)
__device__ __half g_agg[(size_t)NN * DD];        // fp16(agg)
__device__ __half g_wt[(size_t)3 * DD * DD];     // [WQ|WK|WV]^T  [1152(N), 384(K)]
__device__ __half g_wo[(size_t)DD * DD];         // WO^T [384, 384]

// ---------------- PTX helpers (baseline features only; PTX target is compute_103) ----------------
__device__ __forceinline__ uint32_t smem_to_u32(const void* p) {
    uint32_t a;
    asm("{ .reg .u64 t; cvta.to.shared.u64 t, %1; cvt.u32.u64 %0, t; }" : "=r"(a) : "l"(p));
    return a;
}
__device__ __forceinline__ void ldsm_x4(uint32_t* r, uint32_t addr) {
    asm volatile("ldmatrix.sync.aligned.m8n8.x4.shared.b16 {%0,%1,%2,%3}, [%4];"
        : "=r"(r[0]), "=r"(r[1]), "=r"(r[2]), "=r"(r[3]) : "r"(addr));
}
__device__ __forceinline__ void mma_f16(float* c, const uint32_t* a, const uint32_t* b) {
    asm volatile(
        "mma.sync.aligned.m16n8k16.row.col.f32.f16.f16.f32 "
        "{%0,%1,%2,%3}, {%4,%5,%6,%7}, {%8,%9}, {%0,%1,%2,%3};"
        : "+f"(c[0]), "+f"(c[1]), "+f"(c[2]), "+f"(c[3])
        : "r"(a[0]), "r"(a[1]), "r"(a[2]), "r"(a[3]), "r"(b[0]), "r"(b[1]));
}
__device__ __forceinline__ void cp16(uint32_t dst, const void* src, bool valid) {
    int sz = valid ? 16 : 0;
    asm volatile("cp.async.cg.shared.global [%0], [%1], 16, %2;"
        :: "r"(dst), "l"(src), "r"(sz) : "memory");
}

// smem geometry: 2 operand arrays (A, B), 128 rows x 80B pitch, double-buffered
#define PITCH 80
#define ARR   10240          // 128 * 80
#define STG   20480          // 2 * ARR
#define SM_TOTAL (2 * STG)   // 40960

// ---------------- shared mainloop (inlined) ----------------
__device__ __forceinline__ void gemm_mainloop(
    const __half* __restrict__ A, const __half* __restrict__ Bt,
    int M, int rowBase, int btRowBase,
    const uint32_t sb, int tid, int lane, int warp_m, int warp_n,
    float acc[4][4][4])
{
    auto load_stage = [&](int buf, int s) {
        const int k0 = s * 32;
#pragma unroll
        for (int i = 0; i < 4; i++) {
            int id = i * 256 + tid;          // 0..1023
            int arr = id >> 9;               // 0..1
            int cid = id & 511;
            int row = cid >> 2;              // 0..127
            int c = cid & 3;                 // 16B chunk
            uint32_t dst = sb + buf * STG + arr * ARR + row * PITCH + c * 16;
            const __half* src;
            bool valid = true;
            if (arr == 0) {
                int gRow = rowBase + row;
                valid = (gRow < M);
                int gr = valid ? gRow : 0;
                src = A + (size_t)gr * DD + k0 + c * 8;
            } else {
                src = Bt + (size_t)(btRowBase + row) * DD + k0 + c * 8;
            }
            cp16(dst, src, valid);
        }
        asm volatile("cp.async.commit_group;" ::: "memory");
    };

    load_stage(0, 0);

    for (int s = 0; s < 12; s++) {
        asm volatile("cp.async.wait_group 0;" ::: "memory");
        __syncthreads();
        if (s + 1 < 12) load_stage((s + 1) & 1, s + 1);

        const uint32_t st = sb + (s & 1) * STG;
#pragma unroll
        for (int kk = 0; kk < 2; kk++) {
            uint32_t ah[4][4], bh[2][4];
            const int arow = warp_m * 64;
#pragma unroll
            for (int mt = 0; mt < 4; mt++) {
                uint32_t addr = st + (uint32_t)((arow + mt * 16 + (lane & 15)) * PITCH
                              + kk * 32 + ((lane >> 4) & 1) * 16);
                ldsm_x4(ah[mt], addr);
            }
#pragma unroll
            for (int p = 0; p < 2; p++) {
                int grp = lane >> 3;
                int row = warp_n * 32 + (p * 2 + (grp >> 1)) * 8 + (lane & 7);
                uint32_t addr = st + ARR + (uint32_t)(row * PITCH
                              + kk * 32 + (grp & 1) * 16);
                ldsm_x4(bh[p], addr);
            }
#pragma unroll
            for (int mt = 0; mt < 4; mt++) {
#pragma unroll
                for (int nt = 0; nt < 4; nt++) {
                    const uint32_t* B2 = &bh[nt >> 1][(nt & 1) * 2];
                    mma_f16(acc[mt][nt], ah[mt], B2);
                }
            }
        }
    }
}

// ---------------- QKV GEMM: fp16 epilogue ----------------
__global__ __launch_bounds__(256, 2)
void gemm_qkv(const __half* __restrict__ A, const __half* __restrict__ Bt,
              __half* __restrict__ H0, __half* __restrict__ H1, __half* __restrict__ H2,
              int M)
{
    extern __shared__ char smem[];
    const uint32_t sb = smem_to_u32(smem);
    const int tid = threadIdx.x;
    const int wid = tid >> 5;
    const int lane = tid & 31;
    const int warp_m = wid & 1;
    const int warp_n = wid >> 1;
    const int rowBase = blockIdx.y * 128;
    const int mat = blockIdx.x / 3;
    const int colBase = (blockIdx.x % 3) * 128;
    const int btRowBase = blockIdx.x * 128;

    float acc[4][4][4];
#pragma unroll
    for (int i = 0; i < 4; i++)
#pragma unroll
        for (int j = 0; j < 4; j++)
#pragma unroll
            for (int l = 0; l < 4; l++) acc[i][j][l] = 0.0f;

    gemm_mainloop(A, Bt, M, rowBase, btRowBase, sb, tid, lane, warp_m, warp_n, acc);

    __half* H = (mat == 0) ? H0 : (mat == 1 ? H1 : H2);
#pragma unroll
    for (int mt = 0; mt < 4; mt++) {
        int r0 = rowBase + warp_m * 64 + mt * 16 + (lane >> 2);
#pragma unroll
        for (int nt = 0; nt < 4; nt++) {
            int col = colBase + warp_n * 32 + nt * 8 + (lane & 3) * 2;
#pragma unroll
            for (int half = 0; half < 2; half++) {
                int r = r0 + half * 8;
                if (r >= M) continue;
                size_t off = (size_t)r * DD + col;
                __half2 hv = __floats2half2_rn(acc[mt][nt][half * 2],
                                               acc[mt][nt][half * 2 + 1]);
                *reinterpret_cast<__half2*>(H + off) = hv;
            }
        }
    }
}

// ---------------- O GEMM: fp32 + residual epilogue ----------------
__global__ __launch_bounds__(256, 2)
void gemm_o(const __half* __restrict__ A, const __half* __restrict__ Bt,
            float* __restrict__ Cf, int M, const float* __restrict__ resid)
{
    extern __shared__ char smem[];
    const uint32_t sb = smem_to_u32(smem);
    const int tid = threadIdx.x;
    const int wid = tid >> 5;
    const int lane = tid & 31;
    const int warp_m = wid & 1;
    const int warp_n = wid >> 1;
    const int rowBase = blockIdx.y * 128;
    const int colBase = (blockIdx.x % 3) * 128;
    const int btRowBase = blockIdx.x * 128;

    float acc[4][4][4];
#pragma unroll
    for (int i = 0; i < 4; i++)
#pragma unroll
        for (int j = 0; j < 4; j++)
#pragma unroll
            for (int l = 0; l < 4; l++) acc[i][j][l] = 0.0f;

    gemm_mainloop(A, Bt, M, rowBase, btRowBase, sb, tid, lane, warp_m, warp_n, acc);

#pragma unroll
    for (int mt = 0; mt < 4; mt++) {
        int r0 = rowBase + warp_m * 64 + mt * 16 + (lane >> 2);
#pragma unroll
        for (int nt = 0; nt < 4; nt++) {
            int col = colBase + warp_n * 32 + nt * 8 + (lane & 3) * 2;
#pragma unroll
            for (int half = 0; half < 2; half++) {
                int r = r0 + half * 8;
                if (r >= M) continue;
                size_t off = (size_t)r * DD + col;
                float2 v = make_float2(acc[mt][nt][half * 2], acc[mt][nt][half * 2 + 1]);
                float2 rv = *reinterpret_cast<const float2*>(resid + off);
                v.x += rv.x; v.y += rv.y;
                *reinterpret_cast<float2*>(Cf + off) = v;
            }
        }
    }
}

// ---------------- conversions ----------------
__global__ __launch_bounds__(256) void conv_emb(const float* __restrict__ emb) {
    int idx = blockIdx.x * 256 + threadIdx.x;
    if (idx >= NN * DD / 4) return;
    float4 x = reinterpret_cast<const float4*>(emb)[idx];
    __half2 a, b;
    a.x = __float2half_rn(x.x); a.y = __float2half_rn(x.y);
    b.x = __float2half_rn(x.z); b.y = __float2half_rn(x.w);
    uint2 v = make_uint2(*reinterpret_cast<uint32_t*>(&a), *reinterpret_cast<uint32_t*>(&b));
    reinterpret_cast<uint2*>(g_emb)[idx] = v;
}

__global__ __launch_bounds__(256) void conv_weights(
    const float* __restrict__ WQ, const float* __restrict__ WK,
    const float* __restrict__ WV, const float* __restrict__ WO)
{
    int idx = blockIdx.x * 256 + threadIdx.x;
    if (idx >= 4 * DD * DD) return;
    int mat = idx / (DD * DD);
    int rem = idx - mat * (DD * DD);
    int n = rem / DD;
    int k = rem - n * DD;
    const float* W = (mat == 0) ? WQ : (mat == 1 ? WK : (mat == 2 ? WV : WO));
    __half h = __float2half_rn(W[(size_t)k * DD + n]);
    if (mat < 3) g_wt[(size_t)mat * DD * DD + (size_t)n * DD + k] = h;
    else         g_wo[(size_t)n * DD + k] = h;
}

// ---------------- CSR build (side stream) ----------------
__global__ __launch_bounds__(256) void zero_deg() {
    int i = blockIdx.x * 256 + threadIdx.x;
    if (i < NN) g_deg[i] = 0;
}

__global__ __launch_bounds__(256) void hist_kernel(const int* __restrict__ dst) {
    int e = blockIdx.x * 256 + threadIdx.x;
    if (e < EE) atomicAdd(&g_deg[dst[e]], 1);
}

__device__ __forceinline__ int warp_incl_scan(int x, int lane) {
#pragma unroll
    for (int off = 1; off < 32; off <<= 1) {
        int v = __shfl_up_sync(0xffffffffu, x, off);
        if (lane >= off) x += v;
    }
    return x;
}

__global__ __launch_bounds__(1024) void scanA() {
    __shared__ int swarp[32];
    const int tid = threadIdx.x;
    const int w = tid >> 5, lane = tid & 31;
    int idx = blockIdx.x * 1024 + tid;
    int x = (idx < NN) ? g_deg[idx] : 0;
    int incl = warp_incl_scan(x, lane);
    if (lane == 31) swarp[w] = incl;
    __syncthreads();
    if (w == 0) {
        int t = swarp[lane];
        t = warp_incl_scan(t, lane);
        swarp[lane] = t;
    }
    __syncthreads();
    int woff = (w > 0) ? swarp[w - 1] : 0;
    incl += woff;
    if (idx < NN) g_rowptr[idx] = incl;
    if (tid == 1023) g_blocksum[blockIdx.x] = incl;
}

__global__ __launch_bounds__(64) void scanB() {
    __shared__ int sh[64];
    const int tid = threadIdx.x;
    int v = (tid < NSCAN) ? g_blocksum[tid] : 0;
    sh[tid] = v;
    for (int off = 1; off < 64; off <<= 1) {
        __syncthreads();
        int t = (tid >= off) ? sh[tid - off] : 0;
        __syncthreads();
        sh[tid] += t;
    }
    __syncthreads();
    if (tid < NSCAN) g_blocksum[tid] = sh[tid] - v;  // exclusive
    if (tid == 63) g_rowptr[NN] = sh[63];
}

__global__ __launch_bounds__(1024) void scanC() {
    int idx = blockIdx.x * 1024 + threadIdx.x;
    if (idx >= NN) return;
    int ex = g_blocksum[blockIdx.x] + g_rowptr[idx] - g_deg[idx];
    g_rowptr[idx] = ex;
    g_cursor[idx] = ex;
}

__global__ __launch_bounds__(256) void scatter_kernel(
    const int* __restrict__ src, const int* __restrict__ dst,
    const float* __restrict__ eattr)
{
    int e = blockIdx.x * 256 + threadIdx.x;
    if (e >= EE) return;
    int t = dst[e];
    int pos = atomicAdd(&g_cursor[t], 1);
    g_esrc[pos] = src[e];
    g_eea[pos] = eattr[e];
}

// ---------------- fused attention aggregate: warp per (node, head), half2 ----------------
__global__ __launch_bounds__(256) void node_fused(const float* __restrict__ WE) {
    const int gw = blockIdx.x * 8 + (threadIdx.x >> 5);
    const int n = gw >> 1;
    if (n >= NN) return;
    const int h = gw & 1;
    const int lane = threadIdx.x & 31;
    const int hb2 = h * (DHH / 2);                 // head offset in half2 units
    const size_t rowH2 = (size_t)n * (DD / 2) + hb2;

    float2 qv[3], we2[3];
    const __half2* qrow = reinterpret_cast<const __half2*>(g_q) + rowH2;
    const float* weh = WE + h * DHH;
#pragma unroll
    for (int j = 0; j < 3; j++) {
        int f = lane + 32 * j;
        qv[j] = __half22float2(qrow[f]);
        we2[j] = *reinterpret_cast<const float2*>(weh + 2 * f);
    }

    // qe = q_h . WE_h
    float qe = 0.f;
#pragma unroll
    for (int j = 0; j < 3; j++) qe += qv[j].x * we2[j].x + qv[j].y * we2[j].y;
#pragma unroll
    for (int o = 16; o > 0; o >>= 1) qe += __shfl_xor_sync(0xffffffffu, qe, o);

    const int beg = g_rowptr[n];
    const int end = g_rowptr[n + 1];

    float m0 = -3.0e38f, den = 0.f, sexa = 0.f;
    float2 acc[3];
#pragma unroll
    for (int j = 0; j < 3; j++) acc[j] = make_float2(0.f, 0.f);

    const float SCL = 0.07216878364870323f;  // 1/sqrt(192)

    for (int i = beg; i < end; i++) {
        const int s = g_esrc[i];
        const float ea = g_eea[i];
        const __half2* krow = reinterpret_cast<const __half2*>(g_k) + (size_t)s * (DD / 2) + hb2;
        const __half2* vrow = reinterpret_cast<const __half2*>(g_v) + (size_t)s * (DD / 2) + hb2;

        float2 kv[3], vv[3];
#pragma unroll
        for (int j = 0; j < 3; j++) {
            int f = lane + 32 * j;
            kv[j] = __half22float2(krow[f]);
            vv[j] = __half22float2(vrow[f]);
        }
        float ds = 0.f;
#pragma unroll
        for (int j = 0; j < 3; j++) ds += qv[j].x * kv[j].x + qv[j].y * kv[j].y;
#pragma unroll
        for (int o = 16; o > 0; o >>= 1) ds += __shfl_xor_sync(0xffffffffu, ds, o);
        float s0 = (ds + ea * qe) * SCL;

        float nm = fmaxf(m0, s0);
        float sc = __expf(m0 - nm);
        float ex = __expf(s0 - nm);
        den = den * sc + ex;
        sexa = sexa * sc + ex * ea;
#pragma unroll
        for (int j = 0; j < 3; j++) {
            acc[j].x = acc[j].x * sc + ex * vv[j].x;
            acc[j].y = acc[j].y * sc + ex * vv[j].y;
        }
        m0 = nm;
    }

    const float inv = 1.0f / (den + 1e-16f);
    __half2* aout = reinterpret_cast<__half2*>(g_agg) + rowH2;
#pragma unroll
    for (int j = 0; j < 3; j++) {
        int f = lane + 32 * j;
        float ox = (acc[j].x + sexa * we2[j].x) * inv;
        float oy = (acc[j].y + sexa * we2[j].y) * inv;
        aout[f] = __floats2half2_rn(ox, oy);
    }
}

// ---------------- layernorm: warp per row, float4 ----------------
__global__ __launch_bounds__(256) void ln_kernel(
    const float* __restrict__ gw, const float* __restrict__ bw,
    float* __restrict__ out)
{
    const int n = blockIdx.x * 8 + (threadIdx.x >> 5);
    if (n >= NN) return;
    const int lane = threadIdx.x & 31;
    const float4* x = reinterpret_cast<const float4*>(g_tmp + (size_t)n * DD);
    float4 v[3];
    float su = 0.f, sq = 0.f;
#pragma unroll
    for (int j = 0; j < 3; j++) {
        v[j] = x[lane + 32 * j];
        su += v[j].x + v[j].y + v[j].z + v[j].w;
        sq += v[j].x * v[j].x + v[j].y * v[j].y + v[j].z * v[j].z + v[j].w * v[j].w;
    }
#pragma unroll
    for (int o = 16; o > 0; o >>= 1) {
        su += __shfl_xor_sync(0xffffffffu, su, o);
        sq += __shfl_xor_sync(0xffffffffu, sq, o);
    }
    float mu = su * (1.0f / DD);
    float var = sq * (1.0f / DD) - mu * mu;
    float inv = rsqrtf(var + 1e-5f);
    const float4* g4 = reinterpret_cast<const float4*>(gw);
    const float4* b4 = reinterpret_cast<const float4*>(bw);
    float4* o4 = reinterpret_cast<float4*>(out + (size_t)n * DD);
#pragma unroll
    for (int j = 0; j < 3; j++) {
        float4 g = g4[lane + 32 * j];
        float4 b = b4[lane + 32 * j];
        float4 r;
        r.x = (v[j].x - mu) * inv * g.x + b.x;
        r.y = (v[j].y - mu) * inv * g.y + b.y;
        r.z = (v[j].z - mu) * inv * g.z + b.z;
        r.w = (v[j].w - mu) * inv * g.w + b.w;
        o4[lane + 32 * j] = r;
    }
}

// ---------------- launch ----------------
extern "C" void kernel_launch(void* const* d_in, const int* in_sizes, int n_in,
                              void* d_out, int out_size)
{
    const float* emb   = (const float*)d_in[0];
    const int*   eidx  = (const int*)  d_in[1];
    const float* eattr = (const float*)d_in[2];
    const float* WQ    = (const float*)d_in[3];
    const float* WK    = (const float*)d_in[4];
    const float* WV    = (const float*)d_in[5];
    const float* WE    = (const float*)d_in[6];
    const float* WO    = (const float*)d_in[7];
    const float* ln_g  = (const float*)d_in[8];
    const float* ln_b  = (const float*)d_in[9];
    float* out = (float*)d_out;

    const int* src = eidx;
    const int* dst = eidx + EE;

    static bool inited = false;
    static cudaStream_t s_side;
    static cudaEvent_t ev_fork, ev_join, ev_w;
    if (!inited) {
        cudaFuncSetAttribute(gemm_qkv, cudaFuncAttributeMaxDynamicSharedMemorySize, SM_TOTAL);
        cudaFuncSetAttribute(gemm_o,   cudaFuncAttributeMaxDynamicSharedMemorySize, SM_TOTAL);
        cudaStreamCreateWithFlags(&s_side, cudaStreamNonBlocking);
        cudaEventCreateWithFlags(&ev_fork, cudaEventDisableTiming);
        cudaEventCreateWithFlags(&ev_join, cudaEventDisableTiming);
        cudaEventCreateWithFlags(&ev_w, cudaEventDisableTiming);
        inited = true;
    }

    float *dtmp;
    __half *dq, *dk, *dv, *demb, *dagg, *dwt, *dwo;
    cudaGetSymbolAddress((void**)&dq,   g_q);
    cudaGetSymbolAddress((void**)&dk,   g_k);
    cudaGetSymbolAddress((void**)&dv,   g_v);
    cudaGetSymbolAddress((void**)&dtmp, g_tmp);
    cudaGetSymbolAddress((void**)&demb, g_emb);
    cudaGetSymbolAddress((void**)&dagg, g_agg);
    cudaGetSymbolAddress((void**)&dwt,  g_wt);
    cudaGetSymbolAddress((void**)&dwo,  g_wo);

    // ---- fork: weights conversion + CSR build on side stream ----
    cudaEventRecord(ev_fork, 0);
    cudaStreamWaitEvent(s_side, ev_fork, 0);
    conv_weights<<<(4 * DD * DD + 255) / 256, 256, 0, s_side>>>(WQ, WK, WV, WO);
    cudaEventRecord(ev_w, s_side);
    zero_deg<<<(NN + 255) / 256, 256, 0, s_side>>>();
    hist_kernel<<<(EE + 255) / 256, 256, 0, s_side>>>(dst);
    scanA<<<NSCAN, 1024, 0, s_side>>>();
    scanB<<<1, 64, 0, s_side>>>();
    scanC<<<NSCAN, 1024, 0, s_side>>>();
    scatter_kernel<<<(EE + 255) / 256, 256, 0, s_side>>>(src, dst, eattr);
    cudaEventRecord(ev_join, s_side);

    // ---- main stream: emb conversion + QKV projections (fp16 out) ----
    conv_emb<<<(NN * DD / 4 + 255) / 256, 256>>>(emb);
    cudaStreamWaitEvent(0, ev_w, 0);

    const int MT = (NN + 127) / 128;
    gemm_qkv<<<dim3(9, MT), 256, SM_TOTAL>>>(demb, dwt, dq, dk, dv, NN);

    // ---- join, then fused attention ----
    cudaStreamWaitEvent(0, ev_join, 0);
    node_fused<<<(2 * NN + 7) / 8, 256>>>(WE);

    // output projection + residual (fp32 out)
    gemm_o<<<dim3(3, MT), 256, SM_TOTAL>>>(dagg, dwo, dtmp, NN, emb);

    // layernorm -> out
    ln_kernel<<<(NN + 7) / 8, 256>>>(ln_g, ln_b, out);
}

// round 17
// speedup vs baseline: 1.5637x; 1.0544x over previous
#include <cuda_runtime.h>
#include <cuda_fp16.h>
#include <math.h>
#include <stdint.h>

// Problem constants (fixed by the reference)
#define NN 50000
#define EE 200000
#define DD 384
#define HH 2
#define DHH 192

#define SCAN_BLK 1024
#define NSCAN ((NN + SCAN_BLK - 1) / SCAN_BLK)   // 49

// ---------------- device scratch (allocation-free requirement) ----------------
__device__ __half g_q[(size_t)NN * DD];          // fp16 q/k/v
__device__ __half g_k[(size_t)NN * DD];
__device__ __half g_v[(size_t)NN * DD];
__device__ float  g_tmp[(size_t)NN * DD];

__device__ int   g_deg[NN];
__device__ int   g_rowptr[NN + 1];
__device__ int   g_cursor[NN];
__device__ int   g_blocksum[NSCAN];
__device__ int   g_esrc[EE];
__device__ float g_eea[EE];

__device__ __half g_emb[(size_t)NN * DD];        // fp16(A)
__device__ __half g_agg[(size_t)NN * DD];        // fp16(agg)
__device__ __half g_wt[(size_t)3 * DD * DD];     // [WQ|WK|WV]^T  [1152(N), 384(K)]
__device__ __half g_wo[(size_t)DD * DD];         // WO^T [384, 384]

// ---------------- PTX helpers (baseline features only; PTX target is compute_103) ----------------
__device__ __forceinline__ uint32_t smem_to_u32(const void* p) {
    uint32_t a;
    asm("{ .reg .u64 t; cvta.to.shared.u64 t, %1; cvt.u32.u64 %0, t; }" : "=r"(a) : "l"(p));
    return a;
}
__device__ __forceinline__ void ldsm_x4(uint32_t* r, uint32_t addr) {
    asm volatile("ldmatrix.sync.aligned.m8n8.x4.shared.b16 {%0,%1,%2,%3}, [%4];"
        : "=r"(r[0]), "=r"(r[1]), "=r"(r[2]), "=r"(r[3]) : "r"(addr));
}
__device__ __forceinline__ void mma_f16(float* c, const uint32_t* a, const uint32_t* b) {
    asm volatile(
        "mma.sync.aligned.m16n8k16.row.col.f32.f16.f16.f32 "
        "{%0,%1,%2,%3}, {%4,%5,%6,%7}, {%8,%9}, {%0,%1,%2,%3};"
        : "+f"(c[0]), "+f"(c[1]), "+f"(c[2]), "+f"(c[3])
        : "r"(a[0]), "r"(a[1]), "r"(a[2]), "r"(a[3]), "r"(b[0]), "r"(b[1]));
}
__device__ __forceinline__ void cp16(uint32_t dst, const void* src, bool valid) {
    int sz = valid ? 16 : 0;
    asm volatile("cp.async.cg.shared.global [%0], [%1], 16, %2;"
        :: "r"(dst), "l"(src), "r"(sz) : "memory");
}

// smem geometry: 2 operand arrays (A, B), 128 rows x 144B pitch (64 halves + 16B pad),
// double-buffered. 72 KB/CTA -> 2 CTAs/SM (regs binding).
#define KC    64
#define NSTG  (DD / KC)      // 6 stages
#define PITCH 144
#define ARR   18432          // 128 * 144
#define STG   36864          // 2 * ARR
#define SM_TOTAL (2 * STG)   // 73728

// ---------------- shared mainloop (inlined) ----------------
__device__ __forceinline__ void gemm_mainloop(
    const __half* __restrict__ A, const __half* __restrict__ Bt,
    int M, int rowBase, int btRowBase,
    const uint32_t sb, int tid, int lane, int warp_m, int warp_n,
    float acc[4][4][4])
{
    auto load_stage = [&](int buf, int s) {
        const int k0 = s * KC;
#pragma unroll
        for (int i = 0; i < 8; i++) {
            int id = i * 256 + tid;          // 0..2047
            int arr = id >> 10;              // 0..1
            int cid = id & 1023;
            int row = cid >> 3;              // 0..127
            int c = cid & 7;                 // 16B chunk 0..7
            uint32_t dst = sb + buf * STG + arr * ARR + row * PITCH + c * 16;
            const __half* src;
            bool valid = true;
            if (arr == 0) {
                int gRow = rowBase + row;
                valid = (gRow < M);
                int gr = valid ? gRow : 0;
                src = A + (size_t)gr * DD + k0 + c * 8;
            } else {
                src = Bt + (size_t)(btRowBase + row) * DD + k0 + c * 8;
            }
            cp16(dst, src, valid);
        }
        asm volatile("cp.async.commit_group;" ::: "memory");
    };

    load_stage(0, 0);

    for (int s = 0; s < NSTG; s++) {
        asm volatile("cp.async.wait_group 0;" ::: "memory");
        __syncthreads();
        if (s + 1 < NSTG) load_stage((s + 1) & 1, s + 1);

        const uint32_t st = sb + (s & 1) * STG;
#pragma unroll
        for (int kk = 0; kk < 4; kk++) {
            uint32_t ah[4][4], bh[2][4];
            const int arow = warp_m * 64;
#pragma unroll
            for (int mt = 0; mt < 4; mt++) {
                uint32_t addr = st + (uint32_t)((arow + mt * 16 + (lane & 15)) * PITCH
                              + kk * 32 + ((lane >> 4) & 1) * 16);
                ldsm_x4(ah[mt], addr);
            }
#pragma unroll
            for (int p = 0; p < 2; p++) {
                int grp = lane >> 3;
                int row = warp_n * 32 + (p * 2 + (grp >> 1)) * 8 + (lane & 7);
                uint32_t addr = st + ARR + (uint32_t)(row * PITCH
                              + kk * 32 + (grp & 1) * 16);
                ldsm_x4(bh[p], addr);
            }
#pragma unroll
            for (int mt = 0; mt < 4; mt++) {
#pragma unroll
                for (int nt = 0; nt < 4; nt++) {
                    const uint32_t* B2 = &bh[nt >> 1][(nt & 1) * 2];
                    mma_f16(acc[mt][nt], ah[mt], B2);
                }
            }
        }
    }
}

// ---------------- QKV GEMM: fp16 epilogue ----------------
__global__ __launch_bounds__(256, 2)
void gemm_qkv(const __half* __restrict__ A, const __half* __restrict__ Bt,
              __half* __restrict__ H0, __half* __restrict__ H1, __half* __restrict__ H2,
              int M)
{
    extern __shared__ char smem[];
    const uint32_t sb = smem_to_u32(smem);
    const int tid = threadIdx.x;
    const int wid = tid >> 5;
    const int lane = tid & 31;
    const int warp_m = wid & 1;
    const int warp_n = wid >> 1;
    const int rowBase = blockIdx.y * 128;
    const int mat = blockIdx.x / 3;
    const int colBase = (blockIdx.x % 3) * 128;
    const int btRowBase = blockIdx.x * 128;

    float acc[4][4][4];
#pragma unroll
    for (int i = 0; i < 4; i++)
#pragma unroll
        for (int j = 0; j < 4; j++)
#pragma unroll
            for (int l = 0; l < 4; l++) acc[i][j][l] = 0.0f;

    gemm_mainloop(A, Bt, M, rowBase, btRowBase, sb, tid, lane, warp_m, warp_n, acc);

    __half* H = (mat == 0) ? H0 : (mat == 1 ? H1 : H2);
#pragma unroll
    for (int mt = 0; mt < 4; mt++) {
        int r0 = rowBase + warp_m * 64 + mt * 16 + (lane >> 2);
#pragma unroll
        for (int nt = 0; nt < 4; nt++) {
            int col = colBase + warp_n * 32 + nt * 8 + (lane & 3) * 2;
#pragma unroll
            for (int half = 0; half < 2; half++) {
                int r = r0 + half * 8;
                if (r >= M) continue;
                size_t off = (size_t)r * DD + col;
                __half2 hv = __floats2half2_rn(acc[mt][nt][half * 2],
                                               acc[mt][nt][half * 2 + 1]);
                *reinterpret_cast<__half2*>(H + off) = hv;
            }
        }
    }
}

// ---------------- O GEMM: fp32 + residual epilogue ----------------
__global__ __launch_bounds__(256, 2)
void gemm_o(const __half* __restrict__ A, const __half* __restrict__ Bt,
            float* __restrict__ Cf, int M, const float* __restrict__ resid)
{
    extern __shared__ char smem[];
    const uint32_t sb = smem_to_u32(smem);
    const int tid = threadIdx.x;
    const int wid = tid >> 5;
    const int lane = tid & 31;
    const int warp_m = wid & 1;
    const int warp_n = wid >> 1;
    const int rowBase = blockIdx.y * 128;
    const int colBase = (blockIdx.x % 3) * 128;
    const int btRowBase = blockIdx.x * 128;

    float acc[4][4][4];
#pragma unroll
    for (int i = 0; i < 4; i++)
#pragma unroll
        for (int j = 0; j < 4; j++)
#pragma unroll
            for (int l = 0; l < 4; l++) acc[i][j][l] = 0.0f;

    gemm_mainloop(A, Bt, M, rowBase, btRowBase, sb, tid, lane, warp_m, warp_n, acc);

#pragma unroll
    for (int mt = 0; mt < 4; mt++) {
        int r0 = rowBase + warp_m * 64 + mt * 16 + (lane >> 2);
#pragma unroll
        for (int nt = 0; nt < 4; nt++) {
            int col = colBase + warp_n * 32 + nt * 8 + (lane & 3) * 2;
#pragma unroll
            for (int half = 0; half < 2; half++) {
                int r = r0 + half * 8;
                if (r >= M) continue;
                size_t off = (size_t)r * DD + col;
                float2 v = make_float2(acc[mt][nt][half * 2], acc[mt][nt][half * 2 + 1]);
                float2 rv = *reinterpret_cast<const float2*>(resid + off);
                v.x += rv.x; v.y += rv.y;
                *reinterpret_cast<float2*>(Cf + off) = v;
            }
        }
    }
}

// ---------------- conversions ----------------
__global__ __launch_bounds__(256) void conv_emb(const float* __restrict__ emb) {
    int idx = blockIdx.x * 256 + threadIdx.x;
    if (idx >= NN * DD / 4) return;
    float4 x = reinterpret_cast<const float4*>(emb)[idx];
    __half2 a, b;
    a.x = __float2half_rn(x.x); a.y = __float2half_rn(x.y);
    b.x = __float2half_rn(x.z); b.y = __float2half_rn(x.w);
    uint2 v = make_uint2(*reinterpret_cast<uint32_t*>(&a), *reinterpret_cast<uint32_t*>(&b));
    reinterpret_cast<uint2*>(g_emb)[idx] = v;
}

__global__ __launch_bounds__(256) void conv_weights(
    const float* __restrict__ WQ, const float* __restrict__ WK,
    const float* __restrict__ WV, const float* __restrict__ WO)
{
    int idx = blockIdx.x * 256 + threadIdx.x;
    if (idx >= 4 * DD * DD) return;
    int mat = idx / (DD * DD);
    int rem = idx - mat * (DD * DD);
    int n = rem / DD;
    int k = rem - n * DD;
    const float* W = (mat == 0) ? WQ : (mat == 1 ? WK : (mat == 2 ? WV : WO));
    __half h = __float2half_rn(W[(size_t)k * DD + n]);
    if (mat < 3) g_wt[(size_t)mat * DD * DD + (size_t)n * DD + k] = h;
    else         g_wo[(size_t)n * DD + k] = h;
}

// ---------------- CSR build (side stream) ----------------
__global__ __launch_bounds__(256) void zero_deg() {
    int i = blockIdx.x * 256 + threadIdx.x;
    if (i < NN) g_deg[i] = 0;
}

__global__ __launch_bounds__(256) void hist_kernel(const int* __restrict__ dst) {
    int e = blockIdx.x * 256 + threadIdx.x;
    if (e < EE) atomicAdd(&g_deg[dst[e]], 1);
}

__device__ __forceinline__ int warp_incl_scan(int x, int lane) {
#pragma unroll
    for (int off = 1; off < 32; off <<= 1) {
        int v = __shfl_up_sync(0xffffffffu, x, off);
        if (lane >= off) x += v;
    }
    return x;
}

__global__ __launch_bounds__(1024) void scanA() {
    __shared__ int swarp[32];
    const int tid = threadIdx.x;
    const int w = tid >> 5, lane = tid & 31;
    int idx = blockIdx.x * 1024 + tid;
    int x = (idx < NN) ? g_deg[idx] : 0;
    int incl = warp_incl_scan(x, lane);
    if (lane == 31) swarp[w] = incl;
    __syncthreads();
    if (w == 0) {
        int t = swarp[lane];
        t = warp_incl_scan(t, lane);
        swarp[lane] = t;
    }
    __syncthreads();
    int woff = (w > 0) ? swarp[w - 1] : 0;
    incl += woff;
    if (idx < NN) g_rowptr[idx] = incl;
    if (tid == 1023) g_blocksum[blockIdx.x] = incl;
}

__global__ __launch_bounds__(64) void scanB() {
    __shared__ int sh[64];
    const int tid = threadIdx.x;
    int v = (tid < NSCAN) ? g_blocksum[tid] : 0;
    sh[tid] = v;
    for (int off = 1; off < 64; off <<= 1) {
        __syncthreads();
        int t = (tid >= off) ? sh[tid - off] : 0;
        __syncthreads();
        sh[tid] += t;
    }
    __syncthreads();
    if (tid < NSCAN) g_blocksum[tid] = sh[tid] - v;  // exclusive
    if (tid == 63) g_rowptr[NN] = sh[63];
}

__global__ __launch_bounds__(1024) void scanC() {
    int idx = blockIdx.x * 1024 + threadIdx.x;
    if (idx >= NN) return;
    int ex = g_blocksum[blockIdx.x] + g_rowptr[idx] - g_deg[idx];
    g_rowptr[idx] = ex;
    g_cursor[idx] = ex;
}

__global__ __launch_bounds__(256) void scatter_kernel(
    const int* __restrict__ src, const int* __restrict__ dst,
    const float* __restrict__ eattr)
{
    int e = blockIdx.x * 256 + threadIdx.x;
    if (e >= EE) return;
    int t = dst[e];
    int pos = atomicAdd(&g_cursor[t], 1);
    g_esrc[pos] = src[e];
    g_eea[pos] = eattr[e];
}

// ---------------- fused attention aggregate: warp per (node, head), half2 ----------------
__global__ __launch_bounds__(256) void node_fused(const float* __restrict__ WE) {
    const int gw = blockIdx.x * 8 + (threadIdx.x >> 5);
    const int n = gw >> 1;
    if (n >= NN) return;
    const int h = gw & 1;
    const int lane = threadIdx.x & 31;
    const int hb2 = h * (DHH / 2);
    const size_t rowH2 = (size_t)n * (DD / 2) + hb2;

    float2 qv[3], we2[3];
    const __half2* qrow = reinterpret_cast<const __half2*>(g_q) + rowH2;
    const float* weh = WE + h * DHH;
#pragma unroll
    for (int j = 0; j < 3; j++) {
        int f = lane + 32 * j;
        qv[j] = __half22float2(qrow[f]);
        we2[j] = *reinterpret_cast<const float2*>(weh + 2 * f);
    }

    float qe = 0.f;
#pragma unroll
    for (int j = 0; j < 3; j++) qe += qv[j].x * we2[j].x + qv[j].y * we2[j].y;
#pragma unroll
    for (int o = 16; o > 0; o >>= 1) qe += __shfl_xor_sync(0xffffffffu, qe, o);

    const int beg = g_rowptr[n];
    const int end = g_rowptr[n + 1];

    float m0 = -3.0e38f, den = 0.f, sexa = 0.f;
    float2 acc[3];
#pragma unroll
    for (int j = 0; j < 3; j++) acc[j] = make_float2(0.f, 0.f);

    const float SCL = 0.07216878364870323f;  // 1/sqrt(192)

    for (int i = beg; i < end; i++) {
        const int s = g_esrc[i];
        const float ea = g_eea[i];
        const __half2* krow = reinterpret_cast<const __half2*>(g_k) + (size_t)s * (DD / 2) + hb2;
        const __half2* vrow = reinterpret_cast<const __half2*>(g_v) + (size_t)s * (DD / 2) + hb2;

        float2 kv[3], vv[3];
#pragma unroll
        for (int j = 0; j < 3; j++) {
            int f = lane + 32 * j;
            kv[j] = __half22float2(krow[f]);
            vv[j] = __half22float2(vrow[f]);
        }
        float ds = 0.f;
#pragma unroll
        for (int j = 0; j < 3; j++) ds += qv[j].x * kv[j].x + qv[j].y * kv[j].y;
#pragma unroll
        for (int o = 16; o > 0; o >>= 1) ds += __shfl_xor_sync(0xffffffffu, ds, o);
        float s0 = (ds + ea * qe) * SCL;

        float nm = fmaxf(m0, s0);
        float sc = __expf(m0 - nm);
        float ex = __expf(s0 - nm);
        den = den * sc + ex;
        sexa = sexa * sc + ex * ea;
#pragma unroll
        for (int j = 0; j < 3; j++) {
            acc[j].x = acc[j].x * sc + ex * vv[j].x;
            acc[j].y = acc[j].y * sc + ex * vv[j].y;
        }
        m0 = nm;
    }

    const float inv = 1.0f / (den + 1e-16f);
    __half2* aout = reinterpret_cast<__half2*>(g_agg) + rowH2;
#pragma unroll
    for (int j = 0; j < 3; j++) {
        int f = lane + 32 * j;
        float ox = (acc[j].x + sexa * we2[j].x) * inv;
        float oy = (acc[j].y + sexa * we2[j].y) * inv;
        aout[f] = __floats2half2_rn(ox, oy);
    }
}

// ---------------- layernorm: warp per row, float4 ----------------
__global__ __launch_bounds__(256) void ln_kernel(
    const float* __restrict__ gw, const float* __restrict__ bw,
    float* __restrict__ out)
{
    const int n = blockIdx.x * 8 + (threadIdx.x >> 5);
    if (n >= NN) return;
    const int lane = threadIdx.x & 31;
    const float4* x = reinterpret_cast<const float4*>(g_tmp + (size_t)n * DD);
    float4 v[3];
    float su = 0.f, sq = 0.f;
#pragma unroll
    for (int j = 0; j < 3; j++) {
        v[j] = x[lane + 32 * j];
        su += v[j].x + v[j].y + v[j].z + v[j].w;
        sq += v[j].x * v[j].x + v[j].y * v[j].y + v[j].z * v[j].z + v[j].w * v[j].w;
    }
#pragma unroll
    for (int o = 16; o > 0; o >>= 1) {
        su += __shfl_xor_sync(0xffffffffu, su, o);
        sq += __shfl_xor_sync(0xffffffffu, sq, o);
    }
    float mu = su * (1.0f / DD);
    float var = sq * (1.0f / DD) - mu * mu;
    float inv = rsqrtf(var + 1e-5f);
    const float4* g4 = reinterpret_cast<const float4*>(gw);
    const float4* b4 = reinterpret_cast<const float4*>(bw);
    float4* o4 = reinterpret_cast<float4*>(out + (size_t)n * DD);
#pragma unroll
    for (int j = 0; j < 3; j++) {
        float4 g = g4[lane + 32 * j];
        float4 b = b4[lane + 32 * j];
        float4 r;
        r.x = (v[j].x - mu) * inv * g.x + b.x;
        r.y = (v[j].y - mu) * inv * g.y + b.y;
        r.z = (v[j].z - mu) * inv * g.z + b.z;
        r.w = (v[j].w - mu) * inv * g.w + b.w;
        o4[lane + 32 * j] = r;
    }
}

// ---------------- launch ----------------
extern "C" void kernel_launch(void* const* d_in, const int* in_sizes, int n_in,
                              void* d_out, int out_size)
{
    const float* emb   = (const float*)d_in[0];
    const int*   eidx  = (const int*)  d_in[1];
    const float* eattr = (const float*)d_in[2];
    const float* WQ    = (const float*)d_in[3];
    const float* WK    = (const float*)d_in[4];
    const float* WV    = (const float*)d_in[5];
    const float* WE    = (const float*)d_in[6];
    const float* WO    = (const float*)d_in[7];
    const float* ln_g  = (const float*)d_in[8];
    const float* ln_b  = (const float*)d_in[9];
    float* out = (float*)d_out;

    const int* src = eidx;
    const int* dst = eidx + EE;

    static bool inited = false;
    static cudaStream_t s_side;
    static cudaEvent_t ev_fork, ev_join, ev_w;
    if (!inited) {
        cudaFuncSetAttribute(gemm_qkv, cudaFuncAttributeMaxDynamicSharedMemorySize, SM_TOTAL);
        cudaFuncSetAttribute(gemm_o,   cudaFuncAttributeMaxDynamicSharedMemorySize, SM_TOTAL);
        cudaStreamCreateWithFlags(&s_side, cudaStreamNonBlocking);
        cudaEventCreateWithFlags(&ev_fork, cudaEventDisableTiming);
        cudaEventCreateWithFlags(&ev_join, cudaEventDisableTiming);
        cudaEventCreateWithFlags(&ev_w, cudaEventDisableTiming);
        inited = true;
    }

    float *dtmp;
    __half *dq, *dk, *dv, *demb, *dagg, *dwt, *dwo;
    cudaGetSymbolAddress((void**)&dq,   g_q);
    cudaGetSymbolAddress((void**)&dk,   g_k);
    cudaGetSymbolAddress((void**)&dv,   g_v);
    cudaGetSymbolAddress((void**)&dtmp, g_tmp);
    cudaGetSymbolAddress((void**)&demb, g_emb);
    cudaGetSymbolAddress((void**)&dagg, g_agg);
    cudaGetSymbolAddress((void**)&dwt,  g_wt);
    cudaGetSymbolAddress((void**)&dwo,  g_wo);

    // ---- fork: weights conversion + CSR build on side stream ----
    cudaEventRecord(ev_fork, 0);
    cudaStreamWaitEvent(s_side, ev_fork, 0);
    conv_weights<<<(4 * DD * DD + 255) / 256, 256, 0, s_side>>>(WQ, WK, WV, WO);
    cudaEventRecord(ev_w, s_side);
    zero_deg<<<(NN + 255) / 256, 256, 0, s_side>>>();
    hist_kernel<<<(EE + 255) / 256, 256, 0, s_side>>>(dst);
    scanA<<<NSCAN, 1024, 0, s_side>>>();
    scanB<<<1, 64, 0, s_side>>>();
    scanC<<<NSCAN, 1024, 0, s_side>>>();
    scatter_kernel<<<(EE + 255) / 256, 256, 0, s_side>>>(src, dst, eattr);
    cudaEventRecord(ev_join, s_side);

    // ---- main stream: emb conversion + QKV projections (fp16 out) ----
    conv_emb<<<(NN * DD / 4 + 255) / 256, 256>>>(emb);
    cudaStreamWaitEvent(0, ev_w, 0);

    const int MT = (NN + 127) / 128;
    gemm_qkv<<<dim3(9, MT), 256, SM_TOTAL>>>(demb, dwt, dq, dk, dv, NN);

    // ---- join, then fused attention ----
    cudaStreamWaitEvent(0, ev_join, 0);
    node_fused<<<(2 * NN + 7) / 8, 256>>>(WE);

    // output projection + residual (fp32 out)
    gemm_o<<<dim3(3, MT), 256, SM_TOTAL>>>(dagg, dwo, dtmp, NN, emb);

    // layernorm -> out
    ln_kernel<<<(NN + 7) / 8, 256>>>(ln_g, ln_b, out);
}